// round 14
// baseline (speedup 1.0000x reference)
#include <cuda_runtime.h>
#include <cstdint>

#define BB 8
#define LL 256
#define DD 512
#define HH 512
#define NTOT (LL*BB*LL)          // 524288

// Scratch: transposed projections dl_t[b][h][i], dr_t[b][h][i]
__device__ float g_dlt[BB*HH*LL];
__device__ float g_drt[BB*HH*LL];

// ---------------------------------------------------------------------------
// f32x2 packed-math helpers
// ---------------------------------------------------------------------------
typedef unsigned long long u64;

__device__ __forceinline__ u64 pack2(float lo, float hi) {
    u64 r; asm("mov.b64 %0, {%1, %2};" : "=l"(r) : "f"(lo), "f"(hi)); return r;
}
__device__ __forceinline__ void unpack2(u64 v, float& lo, float& hi) {
    asm("mov.b64 {%0, %1}, %2;" : "=f"(lo), "=f"(hi) : "l"(v));
}
__device__ __forceinline__ void ffma2(u64& d, u64 a, u64 b) {
    asm("fma.rn.f32x2 %0, %1, %2, %0;" : "+l"(d) : "l"(a), "l"(b));
}

// ---------------------------------------------------------------------------
// Kernel 1: fused dual GEMM (round-13 version — double-buffered, one sync
// per k-chunk, at the fma-pipe floor). 64h x 64i tile per CTA, 256 threads.
// ---------------------------------------------------------------------------
__global__ __launch_bounds__(256) void dual_gemm_kernel(
    const float* __restrict__ enc,
    const float* __restrict__ Wl,
    const float* __restrict__ Wr)
{
    const int b  = blockIdx.z;
    const int h0 = blockIdx.x * 64;
    const int i0 = blockIdx.y * 64;

    __shared__ float se[2][16][68];   // [buf][k][i] (padded)
    __shared__ float swl[2][16][64];  // [buf][k][h]
    __shared__ float swr[2][16][64];

    const int tid = threadIdx.x;
    const int tx  = tid & 15;      // h group (4 h each)
    const int ty  = tid >> 4;      // i group (4 i each)

    // staging indices
    const int kkW = tid >> 4;          // 0..15  W row
    const int hhW = (tid & 15) << 2;   // 0..60
    const int iiE = tid >> 2;          // 0..63  enc row
    const int kkE = (tid & 3) << 2;    // 0,4,8,12

    u64 accl2[4][2], accr2[4][2];  // [a=i][h-pair]
#pragma unroll
    for (int a = 0; a < 4; a++)
#pragma unroll
        for (int c2 = 0; c2 < 2; c2++) { accl2[a][c2] = 0ull; accr2[a][c2] = 0ull; }

    // preload chunk 0 into registers
    float4 pvl = *(const float4*)&Wl[kkW * HH + h0 + hhW];
    float4 pvr = *(const float4*)&Wr[kkW * HH + h0 + hhW];
    float4 pve = *(const float4*)&enc[(b * LL + i0 + iiE) * DD + kkE];

    int p = 0;
    for (int k0 = 0; k0 < DD; k0 += 16, p ^= 1) {
        // store prefetched chunk into buffer p
        *(float4*)&swl[p][kkW][hhW] = pvl;
        *(float4*)&swr[p][kkW][hhW] = pvr;
        se[p][kkE + 0][iiE] = pve.x;
        se[p][kkE + 1][iiE] = pve.y;
        se[p][kkE + 2][iiE] = pve.z;
        se[p][kkE + 3][iiE] = pve.w;

        // issue next chunk's loads; latency hides under compute below
        if (k0 + 16 < DD) {
            pvl = *(const float4*)&Wl[(k0 + 16 + kkW) * HH + h0 + hhW];
            pvr = *(const float4*)&Wr[(k0 + 16 + kkW) * HH + h0 + hhW];
            pve = *(const float4*)&enc[(b * LL + i0 + iiE) * DD + k0 + 16 + kkE];
        }

        __syncthreads();   // single barrier: stores(p) visible; compute(p-2) done

#pragma unroll
        for (int kk = 0; kk < 16; kk++) {
            float ev[4];
            *(float4*)ev = *(const float4*)&se[p][kk][ty << 2];
            const u64 wl01 = *(const u64*)&swl[p][kk][tx << 2];
            const u64 wl23 = *(const u64*)&swl[p][kk][(tx << 2) + 2];
            const u64 wr01 = *(const u64*)&swr[p][kk][tx << 2];
            const u64 wr23 = *(const u64*)&swr[p][kk][(tx << 2) + 2];
#pragma unroll
            for (int a = 0; a < 4; a++) {
                const u64 ea = pack2(ev[a], ev[a]);
                ffma2(accl2[a][0], ea, wl01);
                ffma2(accl2[a][1], ea, wl23);
                ffma2(accr2[a][0], ea, wr01);
                ffma2(accr2[a][1], ea, wr23);
            }
        }
    }

#pragma unroll
    for (int c2 = 0; c2 < 2; c2++) {
        float l0[4], l1[4], r0[4], r1[4];
#pragma unroll
        for (int a = 0; a < 4; a++) {
            unpack2(accl2[a][c2], l0[a], l1[a]);
            unpack2(accr2[a][c2], r0[a], r1[a]);
        }
        const int h    = h0 + (tx << 2) + (c2 << 1);
        const int base = (b * HH + h) * LL + i0 + (ty << 2);
        *(float4*)&g_dlt[base]      = make_float4(l0[0], l0[1], l0[2], l0[3]);
        *(float4*)&g_dlt[base + LL] = make_float4(l1[0], l1[1], l1[2], l1[3]);
        *(float4*)&g_drt[base]      = make_float4(r0[0], r0[1], r0[2], r0[3]);
        *(float4*)&g_drt[base + LL] = make_float4(r1[0], r1[1], r1[2], r1[3]);
    }
}

// ---------------------------------------------------------------------------
// Threefry2x32, key (0, 42), partitionable path: counter = (0, m),
// output bits = lane0 ^ lane1.
// ---------------------------------------------------------------------------
__device__ __forceinline__ unsigned threefry_bits_partitionable(unsigned m)
{
    const unsigned k0 = 0u, k1 = 42u;
    const unsigned k2 = 0x1BD11BDAu ^ k0 ^ k1;
    unsigned x0 = 0u + k0;
    unsigned x1 = m  + k1;
#define TF_RND(r) { x0 += x1; x1 = __funnelshift_l(x1, x1, r); x1 ^= x0; }
    TF_RND(13) TF_RND(15) TF_RND(26) TF_RND(6)   x0 += k1; x1 += k2 + 1u;
    TF_RND(17) TF_RND(29) TF_RND(16) TF_RND(24)  x0 += k2; x1 += k0 + 2u;
    TF_RND(13) TF_RND(15) TF_RND(26) TF_RND(6)   x0 += k0; x1 += k1 + 3u;
    TF_RND(17) TF_RND(29) TF_RND(16) TF_RND(24)  x0 += k1; x1 += k2 + 4u;
    TF_RND(13) TF_RND(15) TF_RND(26) TF_RND(6)   x0 += k2; x1 += k0 + 5u;
#undef TF_RND
    return x0 ^ x1;
}

__device__ __forceinline__ float tanh_fast(float x)
{
    float y;
    asm("tanh.approx.f32 %0, %1;" : "=f"(y) : "f"(x));
    return y;
}

// ---------------------------------------------------------------------------
// Kernel 2: biaffine + epilogue. 32i x 16j tile per CTA -> 1024 CTAs.
// NOW double-buffered like the GEMM: ONE sync per h-chunk; register prefetch
// unchanged. Math (chunk order, hk order, operands) bit-identical to round 13.
// ---------------------------------------------------------------------------
__global__ __launch_bounds__(256) void biaffine_kernel(
    const float* __restrict__ U,
    const float* __restrict__ logit_bias,
    float* __restrict__ out)
{
    const int b  = blockIdx.z;
    const int i0 = blockIdx.y * 32;
    const int j0 = blockIdx.x * 16;

    __shared__ float sl[2][32][32];   // [buf][h][i]
    __shared__ float sr[2][32][16];   // [buf][h][j]
    __shared__ float su[HH];          // all 512 U values, staged once

    const int tid = threadIdx.x;
    const int tx  = tid & 15;      // j (1 each)
    const int ty  = tid >> 4;      // i group (2 each)

    // staging indices
    const int lhk  = tid >> 3;             // 0..31
    const int lcol = (tid & 7) << 2;       // 0..28
    const int rhk  = tid >> 2;             // 0..31 (tid<128)
    const int rcol = (tid & 3) << 2;       // 0..12

    // stage all of U once (covered by the first barrier)
    for (int idx = tid; idx < HH; idx += 256) su[idx] = U[idx];

    // preload chunk 0
    float4 pl = *(const float4*)&g_dlt[(b * HH + lhk) * LL + i0 + lcol];
    float4 pr;
    if (tid < 128) pr = *(const float4*)&g_drt[(b * HH + rhk) * LL + j0 + rcol];

    float acc[2] = {0.f, 0.f};

    int p = 0;
    for (int h0 = 0; h0 < HH; h0 += 32, p ^= 1) {
        // store prefetched chunk into buffer p
        *(float4*)&sl[p][lhk][lcol] = pl;
        if (tid < 128) *(float4*)&sr[p][rhk][rcol] = pr;

        // issue next chunk's loads; latency hides under compute below
        if (h0 + 32 < HH) {
            pl = *(const float4*)&g_dlt[(b * HH + h0 + 32 + lhk) * LL + i0 + lcol];
            if (tid < 128)
                pr = *(const float4*)&g_drt[(b * HH + h0 + 32 + rhk) * LL + j0 + rcol];
        }

        __syncthreads();   // single barrier per chunk

#pragma unroll
        for (int hk = 0; hk < 32; hk++) {
            float dl[2];
            *(float2*)dl = *(const float2*)&sl[p][hk][ty << 1];
            const float dr = sr[p][hk][tx];
            const float u  = su[h0 + hk];
            acc[0] = fmaf(u, tanh_fast(dl[0] + dr), acc[0]);
            acc[1] = fmaf(u, tanh_fast(dl[1] + dr), acc[1]);
        }
    }

    const float lb = logit_bias[0];

#pragma unroll
    for (int a = 0; a < 2; a++) {
        const int i = i0 + (ty << 1) + a;
        const int j = j0 + tx;
        float x = acc[a] + lb;
        if (i == j) x -= 1e8f;

        const int m = i * (BB * LL) + b * LL + j;   // [L,B,L] flat index

        // mask_scores
        out[NTOT + m] = x;

        // p = sigmoid(x)
        const float pp = 1.0f / (1.0f + expf(-x));

        // entropy = p*softplus(-x) + (1-p)*softplus(x)
        const float e  = expf(-fabsf(x));
        const float l1 = log1pf(e);
        const float sp_pos = fmaxf(x, 0.f) + l1;   // softplus(x)
        const float sp_neg = fmaxf(-x, 0.f) + l1;  // softplus(-x)
        out[2 * NTOT + m] = pp * sp_neg + (1.0f - pp) * sp_pos;

        // bernoulli sample, JAX partitionable threefry (key=42)
        const unsigned bits = threefry_bits_partitionable((unsigned)m);
        const float u01 = __uint_as_float((bits >> 9) | 0x3f800000u) - 1.0f;
        out[m] = (u01 < pp) ? 1.0f : 0.0f;
    }
}

// ---------------------------------------------------------------------------
extern "C" void kernel_launch(void* const* d_in, const int* in_sizes, int n_in,
                              void* d_out, int out_size)
{
    const float* enc  = (const float*)d_in[0];
    const float* Wl   = (const float*)d_in[1];
    const float* Wr   = (const float*)d_in[2];
    const float* U    = (const float*)d_in[3];
    const float* bias = (const float*)d_in[4];
    float* out = (float*)d_out;

    dim3 g1(HH / 64, LL / 64, BB);   // 8 x 4 x 8 = 256 CTAs
    dual_gemm_kernel<<<g1, 256>>>(enc, Wl, Wr);

    dim3 g2(LL / 16, LL / 32, BB);   // 16 x 8 x 8 = 1024 CTAs
    biaffine_kernel<<<g2, 256>>>(U, bias, out);
}

// round 15
// speedup vs baseline: 1.6676x; 1.6676x over previous
#include <cuda_runtime.h>
#include <cstdint>

#define BB 8
#define LL 256
#define DD 512
#define HH 512
#define NTOT (LL*BB*LL)          // 524288

// Scratch: transposed projections dl_t[b][h][i], dr_t[b][h][i]
__device__ float g_dlt[BB*HH*LL];
__device__ float g_drt[BB*HH*LL];

// ---------------------------------------------------------------------------
// f32x2 packed-math helpers
// ---------------------------------------------------------------------------
typedef unsigned long long u64;

__device__ __forceinline__ u64 pack2(float lo, float hi) {
    u64 r; asm("mov.b64 %0, {%1, %2};" : "=l"(r) : "f"(lo), "f"(hi)); return r;
}
__device__ __forceinline__ void unpack2(u64 v, float& lo, float& hi) {
    asm("mov.b64 {%0, %1}, %2;" : "=f"(lo), "=f"(hi) : "l"(v));
}
__device__ __forceinline__ void ffma2(u64& d, u64 a, u64 b) {
    asm("fma.rn.f32x2 %0, %1, %2, %0;" : "+l"(d) : "l"(a), "l"(b));
}

// ---------------------------------------------------------------------------
// Kernel 1: fused dual GEMM (round-13 version — double-buffered, one sync
// per k-chunk, at the fma-pipe floor). 64h x 64i tile per CTA, 256 threads.
// ---------------------------------------------------------------------------
__global__ __launch_bounds__(256) void dual_gemm_kernel(
    const float* __restrict__ enc,
    const float* __restrict__ Wl,
    const float* __restrict__ Wr)
{
    const int b  = blockIdx.z;
    const int h0 = blockIdx.x * 64;
    const int i0 = blockIdx.y * 64;

    __shared__ float se[2][16][68];   // [buf][k][i] (padded)
    __shared__ float swl[2][16][64];  // [buf][k][h]
    __shared__ float swr[2][16][64];

    const int tid = threadIdx.x;
    const int tx  = tid & 15;      // h group (4 h each)
    const int ty  = tid >> 4;      // i group (4 i each)

    // staging indices
    const int kkW = tid >> 4;          // 0..15  W row
    const int hhW = (tid & 15) << 2;   // 0..60
    const int iiE = tid >> 2;          // 0..63  enc row
    const int kkE = (tid & 3) << 2;    // 0,4,8,12

    u64 accl2[4][2], accr2[4][2];  // [a=i][h-pair]
#pragma unroll
    for (int a = 0; a < 4; a++)
#pragma unroll
        for (int c2 = 0; c2 < 2; c2++) { accl2[a][c2] = 0ull; accr2[a][c2] = 0ull; }

    // preload chunk 0 into registers
    float4 pvl = *(const float4*)&Wl[kkW * HH + h0 + hhW];
    float4 pvr = *(const float4*)&Wr[kkW * HH + h0 + hhW];
    float4 pve = *(const float4*)&enc[(b * LL + i0 + iiE) * DD + kkE];

    int p = 0;
    for (int k0 = 0; k0 < DD; k0 += 16, p ^= 1) {
        // store prefetched chunk into buffer p
        *(float4*)&swl[p][kkW][hhW] = pvl;
        *(float4*)&swr[p][kkW][hhW] = pvr;
        se[p][kkE + 0][iiE] = pve.x;
        se[p][kkE + 1][iiE] = pve.y;
        se[p][kkE + 2][iiE] = pve.z;
        se[p][kkE + 3][iiE] = pve.w;

        // issue next chunk's loads; latency hides under compute below
        if (k0 + 16 < DD) {
            pvl = *(const float4*)&Wl[(k0 + 16 + kkW) * HH + h0 + hhW];
            pvr = *(const float4*)&Wr[(k0 + 16 + kkW) * HH + h0 + hhW];
            pve = *(const float4*)&enc[(b * LL + i0 + iiE) * DD + k0 + 16 + kkE];
        }

        __syncthreads();   // single barrier: stores(p) visible; compute(p-2) done

#pragma unroll
        for (int kk = 0; kk < 16; kk++) {
            float ev[4];
            *(float4*)ev = *(const float4*)&se[p][kk][ty << 2];
            const u64 wl01 = *(const u64*)&swl[p][kk][tx << 2];
            const u64 wl23 = *(const u64*)&swl[p][kk][(tx << 2) + 2];
            const u64 wr01 = *(const u64*)&swr[p][kk][tx << 2];
            const u64 wr23 = *(const u64*)&swr[p][kk][(tx << 2) + 2];
#pragma unroll
            for (int a = 0; a < 4; a++) {
                const u64 ea = pack2(ev[a], ev[a]);
                ffma2(accl2[a][0], ea, wl01);
                ffma2(accl2[a][1], ea, wl23);
                ffma2(accr2[a][0], ea, wr01);
                ffma2(accr2[a][1], ea, wr23);
            }
        }
    }

#pragma unroll
    for (int c2 = 0; c2 < 2; c2++) {
        float l0[4], l1[4], r0[4], r1[4];
#pragma unroll
        for (int a = 0; a < 4; a++) {
            unpack2(accl2[a][c2], l0[a], l1[a]);
            unpack2(accr2[a][c2], r0[a], r1[a]);
        }
        const int h    = h0 + (tx << 2) + (c2 << 1);
        const int base = (b * HH + h) * LL + i0 + (ty << 2);
        *(float4*)&g_dlt[base]      = make_float4(l0[0], l0[1], l0[2], l0[3]);
        *(float4*)&g_dlt[base + LL] = make_float4(l1[0], l1[1], l1[2], l1[3]);
        *(float4*)&g_drt[base]      = make_float4(r0[0], r0[1], r0[2], r0[3]);
        *(float4*)&g_drt[base + LL] = make_float4(r1[0], r1[1], r1[2], r1[3]);
    }
}

// ---------------------------------------------------------------------------
// Threefry2x32, key (0, 42), partitionable path: counter = (0, m),
// output bits = lane0 ^ lane1.
// ---------------------------------------------------------------------------
__device__ __forceinline__ unsigned threefry_bits_partitionable(unsigned m)
{
    const unsigned k0 = 0u, k1 = 42u;
    const unsigned k2 = 0x1BD11BDAu ^ k0 ^ k1;
    unsigned x0 = 0u + k0;
    unsigned x1 = m  + k1;
#define TF_RND(r) { x0 += x1; x1 = __funnelshift_l(x1, x1, r); x1 ^= x0; }
    TF_RND(13) TF_RND(15) TF_RND(26) TF_RND(6)   x0 += k1; x1 += k2 + 1u;
    TF_RND(17) TF_RND(29) TF_RND(16) TF_RND(24)  x0 += k2; x1 += k0 + 2u;
    TF_RND(13) TF_RND(15) TF_RND(26) TF_RND(6)   x0 += k0; x1 += k1 + 3u;
    TF_RND(17) TF_RND(29) TF_RND(16) TF_RND(24)  x0 += k1; x1 += k2 + 4u;
    TF_RND(13) TF_RND(15) TF_RND(26) TF_RND(6)   x0 += k2; x1 += k0 + 5u;
#undef TF_RND
    return x0 ^ x1;
}

__device__ __forceinline__ float tanh_fast(float x)
{
    float y;
    asm("tanh.approx.f32 %0, %1;" : "=f"(y) : "f"(x));
    return y;
}

// ---------------------------------------------------------------------------
// Kernel 2: biaffine + epilogue. 32i x 16j tile per CTA -> 1024 CTAs.
// Double-buffered with STATIC buffers (sl0/sl1, sr0/sr1; loop unrolled x2 so
// every smem address is a compile-time constant — round 14's dynamic-index
// regression avoided). One barrier per 32-h chunk. Math order bit-identical
// to rounds 12/13.
// ---------------------------------------------------------------------------
__global__ __launch_bounds__(256) void biaffine_kernel(
    const float* __restrict__ U,
    const float* __restrict__ logit_bias,
    float* __restrict__ out)
{
    const int b  = blockIdx.z;
    const int i0 = blockIdx.y * 32;
    const int j0 = blockIdx.x * 16;

    __shared__ float sl0[32][32], sl1[32][32];   // [h][i]
    __shared__ float sr0[32][16], sr1[32][16];   // [h][j]
    __shared__ float su[HH];                     // all 512 U values

    const int tid = threadIdx.x;
    const int tx  = tid & 15;      // j (1 each)
    const int ty  = tid >> 4;      // i group (2 each)

    // staging indices
    const int lhk  = tid >> 3;             // 0..31
    const int lcol = (tid & 7) << 2;       // 0..28
    const int rhk  = tid >> 2;             // 0..31 (tid<128)
    const int rcol = (tid & 3) << 2;       // 0..12

    const float* gl = &g_dlt[b * HH * LL + lhk * LL + i0 + lcol];
    const float* gr = &g_drt[b * HH * LL + rhk * LL + j0 + rcol];

    // stage all of U once (covered by the first barrier)
    for (int idx = tid; idx < HH; idx += 256) su[idx] = U[idx];

    // preload chunk 0
    float4 pl = *(const float4*)gl;
    float4 pr;
    if (tid < 128) pr = *(const float4*)gr;

    float acc[2] = {0.f, 0.f};

#pragma unroll 1
    for (int h0 = 0; h0 < HH; h0 += 64) {
        // ---- chunk A (h0 .. h0+31) -> buffers 0 ----
        *(float4*)&sl0[lhk][lcol] = pl;
        if (tid < 128) *(float4*)&sr0[rhk][rcol] = pr;
        // prefetch chunk B
        pl = *(const float4*)(gl + (h0 + 32) * LL);
        if (tid < 128) pr = *(const float4*)(gr + (h0 + 32) * LL);
        __syncthreads();

#pragma unroll
        for (int hk = 0; hk < 32; hk++) {
            float dl[2];
            *(float2*)dl = *(const float2*)&sl0[hk][ty << 1];
            const float dr = sr0[hk][tx];
            const float u  = su[h0 + hk];
            acc[0] = fmaf(u, tanh_fast(dl[0] + dr), acc[0]);
            acc[1] = fmaf(u, tanh_fast(dl[1] + dr), acc[1]);
        }

        // ---- chunk B (h0+32 .. h0+63) -> buffers 1 ----
        *(float4*)&sl1[lhk][lcol] = pl;
        if (tid < 128) *(float4*)&sr1[rhk][rcol] = pr;
        // prefetch next pair's chunk A
        if (h0 + 64 < HH) {
            pl = *(const float4*)(gl + (h0 + 64) * LL);
            if (tid < 128) pr = *(const float4*)(gr + (h0 + 64) * LL);
        }
        __syncthreads();

#pragma unroll
        for (int hk = 0; hk < 32; hk++) {
            float dl[2];
            *(float2*)dl = *(const float2*)&sl1[hk][ty << 1];
            const float dr = sr1[hk][tx];
            const float u  = su[h0 + 32 + hk];
            acc[0] = fmaf(u, tanh_fast(dl[0] + dr), acc[0]);
            acc[1] = fmaf(u, tanh_fast(dl[1] + dr), acc[1]);
        }
    }

    const float lb = logit_bias[0];

#pragma unroll
    for (int a = 0; a < 2; a++) {
        const int i = i0 + (ty << 1) + a;
        const int j = j0 + tx;
        float x = acc[a] + lb;
        if (i == j) x -= 1e8f;

        const int m = i * (BB * LL) + b * LL + j;   // [L,B,L] flat index

        // mask_scores
        out[NTOT + m] = x;

        // p = sigmoid(x)
        const float pp = 1.0f / (1.0f + expf(-x));

        // entropy = p*softplus(-x) + (1-p)*softplus(x)
        const float e  = expf(-fabsf(x));
        const float l1 = log1pf(e);
        const float sp_pos = fmaxf(x, 0.f) + l1;   // softplus(x)
        const float sp_neg = fmaxf(-x, 0.f) + l1;  // softplus(-x)
        out[2 * NTOT + m] = pp * sp_neg + (1.0f - pp) * sp_pos;

        // bernoulli sample, JAX partitionable threefry (key=42)
        const unsigned bits = threefry_bits_partitionable((unsigned)m);
        const float u01 = __uint_as_float((bits >> 9) | 0x3f800000u) - 1.0f;
        out[m] = (u01 < pp) ? 1.0f : 0.0f;
    }
}

// ---------------------------------------------------------------------------
extern "C" void kernel_launch(void* const* d_in, const int* in_sizes, int n_in,
                              void* d_out, int out_size)
{
    const float* enc  = (const float*)d_in[0];
    const float* Wl   = (const float*)d_in[1];
    const float* Wr   = (const float*)d_in[2];
    const float* U    = (const float*)d_in[3];
    const float* bias = (const float*)d_in[4];
    float* out = (float*)d_out;

    dim3 g1(HH / 64, LL / 64, BB);   // 8 x 4 x 8 = 256 CTAs
    dual_gemm_kernel<<<g1, 256>>>(enc, Wl, Wr);

    dim3 g2(LL / 16, LL / 32, BB);   // 16 x 8 x 8 = 1024 CTAs
    biaffine_kernel<<<g2, 256>>>(U, bias, out);
}

// round 16
// speedup vs baseline: 1.6707x; 1.0019x over previous
#include <cuda_runtime.h>
#include <cstdint>

#define BB 8
#define LL 256
#define DD 512
#define HH 512
#define NTOT (LL*BB*LL)          // 524288

// Scratch: transposed projections dl_t[b][h][i], dr_t[b][h][i]
__device__ float g_dlt[BB*HH*LL];
__device__ float g_drt[BB*HH*LL];

// ---------------------------------------------------------------------------
// f32x2 packed-math helpers
// ---------------------------------------------------------------------------
typedef unsigned long long u64;

__device__ __forceinline__ u64 pack2(float lo, float hi) {
    u64 r; asm("mov.b64 %0, {%1, %2};" : "=l"(r) : "f"(lo), "f"(hi)); return r;
}
__device__ __forceinline__ void unpack2(u64 v, float& lo, float& hi) {
    asm("mov.b64 {%0, %1}, %2;" : "=f"(lo), "=f"(hi) : "l"(v));
}
__device__ __forceinline__ void ffma2(u64& d, u64 a, u64 b) {
    asm("fma.rn.f32x2 %0, %1, %2, %0;" : "+l"(d) : "l"(a), "l"(b));
}

// ---------------------------------------------------------------------------
// Kernel 1: fused dual GEMM (round-13/15 version — double-buffered, one sync
// per k-chunk, at the fma-pipe floor). 64h x 64i tile per CTA, 256 threads.
// PDL: triggers dependent launch at block start (max scheduling overlap;
// data safety comes from the consumer's griddepcontrol.wait).
// ---------------------------------------------------------------------------
__global__ __launch_bounds__(256) void dual_gemm_kernel(
    const float* __restrict__ enc,
    const float* __restrict__ Wl,
    const float* __restrict__ Wr)
{
    asm volatile("griddepcontrol.launch_dependents;");

    const int b  = blockIdx.z;
    const int h0 = blockIdx.x * 64;
    const int i0 = blockIdx.y * 64;

    __shared__ float se[2][16][68];   // [buf][k][i] (padded)
    __shared__ float swl[2][16][64];  // [buf][k][h]
    __shared__ float swr[2][16][64];

    const int tid = threadIdx.x;
    const int tx  = tid & 15;      // h group (4 h each)
    const int ty  = tid >> 4;      // i group (4 i each)

    // staging indices
    const int kkW = tid >> 4;          // 0..15  W row
    const int hhW = (tid & 15) << 2;   // 0..60
    const int iiE = tid >> 2;          // 0..63  enc row
    const int kkE = (tid & 3) << 2;    // 0,4,8,12

    u64 accl2[4][2], accr2[4][2];  // [a=i][h-pair]
#pragma unroll
    for (int a = 0; a < 4; a++)
#pragma unroll
        for (int c2 = 0; c2 < 2; c2++) { accl2[a][c2] = 0ull; accr2[a][c2] = 0ull; }

    // preload chunk 0 into registers
    float4 pvl = *(const float4*)&Wl[kkW * HH + h0 + hhW];
    float4 pvr = *(const float4*)&Wr[kkW * HH + h0 + hhW];
    float4 pve = *(const float4*)&enc[(b * LL + i0 + iiE) * DD + kkE];

    int p = 0;
    for (int k0 = 0; k0 < DD; k0 += 16, p ^= 1) {
        // store prefetched chunk into buffer p
        *(float4*)&swl[p][kkW][hhW] = pvl;
        *(float4*)&swr[p][kkW][hhW] = pvr;
        se[p][kkE + 0][iiE] = pve.x;
        se[p][kkE + 1][iiE] = pve.y;
        se[p][kkE + 2][iiE] = pve.z;
        se[p][kkE + 3][iiE] = pve.w;

        // issue next chunk's loads; latency hides under compute below
        if (k0 + 16 < DD) {
            pvl = *(const float4*)&Wl[(k0 + 16 + kkW) * HH + h0 + hhW];
            pvr = *(const float4*)&Wr[(k0 + 16 + kkW) * HH + h0 + hhW];
            pve = *(const float4*)&enc[(b * LL + i0 + iiE) * DD + k0 + 16 + kkE];
        }

        __syncthreads();   // single barrier: stores(p) visible; compute(p-2) done

#pragma unroll
        for (int kk = 0; kk < 16; kk++) {
            float ev[4];
            *(float4*)ev = *(const float4*)&se[p][kk][ty << 2];
            const u64 wl01 = *(const u64*)&swl[p][kk][tx << 2];
            const u64 wl23 = *(const u64*)&swl[p][kk][(tx << 2) + 2];
            const u64 wr01 = *(const u64*)&swr[p][kk][tx << 2];
            const u64 wr23 = *(const u64*)&swr[p][kk][(tx << 2) + 2];
#pragma unroll
            for (int a = 0; a < 4; a++) {
                const u64 ea = pack2(ev[a], ev[a]);
                ffma2(accl2[a][0], ea, wl01);
                ffma2(accl2[a][1], ea, wl23);
                ffma2(accr2[a][0], ea, wr01);
                ffma2(accr2[a][1], ea, wr23);
            }
        }
    }

#pragma unroll
    for (int c2 = 0; c2 < 2; c2++) {
        float l0[4], l1[4], r0[4], r1[4];
#pragma unroll
        for (int a = 0; a < 4; a++) {
            unpack2(accl2[a][c2], l0[a], l1[a]);
            unpack2(accr2[a][c2], r0[a], r1[a]);
        }
        const int h    = h0 + (tx << 2) + (c2 << 1);
        const int base = (b * HH + h) * LL + i0 + (ty << 2);
        *(float4*)&g_dlt[base]      = make_float4(l0[0], l0[1], l0[2], l0[3]);
        *(float4*)&g_dlt[base + LL] = make_float4(l1[0], l1[1], l1[2], l1[3]);
        *(float4*)&g_drt[base]      = make_float4(r0[0], r0[1], r0[2], r0[3]);
        *(float4*)&g_drt[base + LL] = make_float4(r1[0], r1[1], r1[2], r1[3]);
    }
}

// ---------------------------------------------------------------------------
// Threefry2x32, key (0, 42), partitionable path: counter = (0, m),
// output bits = lane0 ^ lane1.
// ---------------------------------------------------------------------------
__device__ __forceinline__ unsigned threefry_bits_partitionable(unsigned m)
{
    const unsigned k0 = 0u, k1 = 42u;
    const unsigned k2 = 0x1BD11BDAu ^ k0 ^ k1;
    unsigned x0 = 0u + k0;
    unsigned x1 = m  + k1;
#define TF_RND(r) { x0 += x1; x1 = __funnelshift_l(x1, x1, r); x1 ^= x0; }
    TF_RND(13) TF_RND(15) TF_RND(26) TF_RND(6)   x0 += k1; x1 += k2 + 1u;
    TF_RND(17) TF_RND(29) TF_RND(16) TF_RND(24)  x0 += k2; x1 += k0 + 2u;
    TF_RND(13) TF_RND(15) TF_RND(26) TF_RND(6)   x0 += k0; x1 += k1 + 3u;
    TF_RND(17) TF_RND(29) TF_RND(16) TF_RND(24)  x0 += k1; x1 += k2 + 4u;
    TF_RND(13) TF_RND(15) TF_RND(26) TF_RND(6)   x0 += k2; x1 += k0 + 5u;
#undef TF_RND
    return x0 ^ x1;
}

__device__ __forceinline__ float tanh_fast(float x)
{
    float y;
    asm("tanh.approx.f32 %0, %1;" : "=f"(y) : "f"(x));
    return y;
}

// ---------------------------------------------------------------------------
// Kernel 2: biaffine + epilogue (round-15 version, bit-identical math).
// PDL: stages U and computes indices BEFORE griddepcontrol.wait, so the
// prologue runs under the GEMM tail; the wait guarantees g_dlt/g_drt are
// complete and visible before the first prefetch.
// ---------------------------------------------------------------------------
__global__ __launch_bounds__(256) void biaffine_kernel(
    const float* __restrict__ U,
    const float* __restrict__ logit_bias,
    float* __restrict__ out)
{
    const int b  = blockIdx.z;
    const int i0 = blockIdx.y * 32;
    const int j0 = blockIdx.x * 16;

    __shared__ float sl0[32][32], sl1[32][32];   // [h][i]
    __shared__ float sr0[32][16], sr1[32][16];   // [h][j]
    __shared__ float su[HH];                     // all 512 U values

    const int tid = threadIdx.x;
    const int tx  = tid & 15;      // j (1 each)
    const int ty  = tid >> 4;      // i group (2 each)

    // staging indices
    const int lhk  = tid >> 3;             // 0..31
    const int lcol = (tid & 7) << 2;       // 0..28
    const int rhk  = tid >> 2;             // 0..31 (tid<128)
    const int rcol = (tid & 3) << 2;       // 0..12

    const float* gl = &g_dlt[b * HH * LL + lhk * LL + i0 + lcol];
    const float* gr = &g_drt[b * HH * LL + rhk * LL + j0 + rcol];

    // stage all of U (input, not produced by the GEMM) before the wait
    for (int idx = tid; idx < HH; idx += 256) su[idx] = U[idx];
    const float lb = logit_bias[0];

    // wait for the producer grid's completion + memory flush
    asm volatile("griddepcontrol.wait;" ::: "memory");

    // preload chunk 0
    float4 pl = *(const float4*)gl;
    float4 pr;
    if (tid < 128) pr = *(const float4*)gr;

    float acc[2] = {0.f, 0.f};

#pragma unroll 1
    for (int h0 = 0; h0 < HH; h0 += 64) {
        // ---- chunk A (h0 .. h0+31) -> buffers 0 ----
        *(float4*)&sl0[lhk][lcol] = pl;
        if (tid < 128) *(float4*)&sr0[rhk][rcol] = pr;
        // prefetch chunk B
        pl = *(const float4*)(gl + (h0 + 32) * LL);
        if (tid < 128) pr = *(const float4*)(gr + (h0 + 32) * LL);
        __syncthreads();

#pragma unroll
        for (int hk = 0; hk < 32; hk++) {
            float dl[2];
            *(float2*)dl = *(const float2*)&sl0[hk][ty << 1];
            const float dr = sr0[hk][tx];
            const float u  = su[h0 + hk];
            acc[0] = fmaf(u, tanh_fast(dl[0] + dr), acc[0]);
            acc[1] = fmaf(u, tanh_fast(dl[1] + dr), acc[1]);
        }

        // ---- chunk B (h0+32 .. h0+63) -> buffers 1 ----
        *(float4*)&sl1[lhk][lcol] = pl;
        if (tid < 128) *(float4*)&sr1[rhk][rcol] = pr;
        // prefetch next pair's chunk A
        if (h0 + 64 < HH) {
            pl = *(const float4*)(gl + (h0 + 64) * LL);
            if (tid < 128) pr = *(const float4*)(gr + (h0 + 64) * LL);
        }
        __syncthreads();

#pragma unroll
        for (int hk = 0; hk < 32; hk++) {
            float dl[2];
            *(float2*)dl = *(const float2*)&sl1[hk][ty << 1];
            const float dr = sr1[hk][tx];
            const float u  = su[h0 + 32 + hk];
            acc[0] = fmaf(u, tanh_fast(dl[0] + dr), acc[0]);
            acc[1] = fmaf(u, tanh_fast(dl[1] + dr), acc[1]);
        }
    }

#pragma unroll
    for (int a = 0; a < 2; a++) {
        const int i = i0 + (ty << 1) + a;
        const int j = j0 + tx;
        float x = acc[a] + lb;
        if (i == j) x -= 1e8f;

        const int m = i * (BB * LL) + b * LL + j;   // [L,B,L] flat index

        // mask_scores
        out[NTOT + m] = x;

        // p = sigmoid(x)
        const float pp = 1.0f / (1.0f + expf(-x));

        // entropy = p*softplus(-x) + (1-p)*softplus(x)
        const float e  = expf(-fabsf(x));
        const float l1 = log1pf(e);
        const float sp_pos = fmaxf(x, 0.f) + l1;   // softplus(x)
        const float sp_neg = fmaxf(-x, 0.f) + l1;  // softplus(-x)
        out[2 * NTOT + m] = pp * sp_neg + (1.0f - pp) * sp_pos;

        // bernoulli sample, JAX partitionable threefry (key=42)
        const unsigned bits = threefry_bits_partitionable((unsigned)m);
        const float u01 = __uint_as_float((bits >> 9) | 0x3f800000u) - 1.0f;
        out[m] = (u01 < pp) ? 1.0f : 0.0f;
    }
}

// ---------------------------------------------------------------------------
extern "C" void kernel_launch(void* const* d_in, const int* in_sizes, int n_in,
                              void* d_out, int out_size)
{
    const float* enc  = (const float*)d_in[0];
    const float* Wl   = (const float*)d_in[1];
    const float* Wr   = (const float*)d_in[2];
    const float* U    = (const float*)d_in[3];
    const float* bias = (const float*)d_in[4];
    float* out = (float*)d_out;

    dim3 g1(HH / 64, LL / 64, BB);   // 8 x 4 x 8 = 256 CTAs
    dual_gemm_kernel<<<g1, 256>>>(enc, Wl, Wr);

    // biaffine with Programmatic Dependent Launch: schedulable during the
    // GEMM; data dependency enforced in-kernel by griddepcontrol.wait.
    dim3 g2(LL / 16, LL / 32, BB);   // 16 x 8 x 8 = 1024 CTAs
    cudaLaunchConfig_t cfg = {};
    cfg.gridDim  = g2;
    cfg.blockDim = dim3(256, 1, 1);
    cfg.dynamicSmemBytes = 0;
    cfg.stream = 0;
    cudaLaunchAttribute attr[1];
    attr[0].id = cudaLaunchAttributeProgrammaticStreamSerialization;
    attr[0].val.programmaticStreamSerializationAllowed = 1;
    cfg.attrs = attr;
    cfg.numAttrs = 1;
    cudaLaunchKernelEx(&cfg, biaffine_kernel, U, bias, out);
}